// round 11
// baseline (speedup 1.0000x reference)
#include <cuda_runtime.h>
#include <cuda_fp16.h>
#include <cstdint>

#define CIN 256
#define COUT 256
#define HH 56
#define WW 56
#define NN 8
#define KKER 9
#define HWSZ (HH*WW)            // 3136
#define M_TOTAL (NN*HWSZ)       // 25088
#define KD (KKER*CIN)           // 2304

// Scratch (device globals — no runtime allocation allowed)
__device__ __half g_xh[(size_t)NN*HWSZ*CIN];        // 12.8 MB fp16 NHWC
__device__ __half g_Vh[(size_t)M_TOTAL*KD];         // 115.6 MB fp16
__device__ __half g_Bh[(size_t)COUT*KD];            // 1.18 MB fp16

// ---------------------------------------------------------------------------
// helpers
// ---------------------------------------------------------------------------
__device__ __forceinline__ uint32_t smem_u32(const void* p) {
    uint32_t a;
    asm("{ .reg .u64 t; cvta.to.shared.u64 t, %1; cvt.u32.u64 %0, t; }"
        : "=r"(a) : "l"(p));
    return a;
}
__device__ __forceinline__ void cp_async16(uint32_t saddr, const void* gptr) {
    asm volatile("cp.async.cg.shared.global [%0], [%1], 16;"
                 :: "r"(saddr), "l"(__cvta_generic_to_global(gptr)) : "memory");
}
__device__ __forceinline__ void cp_commit() {
    asm volatile("cp.async.commit_group;" ::: "memory");
}
template <int N>
__device__ __forceinline__ void cp_wait() {
    asm volatile("cp.async.wait_group %0;" :: "n"(N) : "memory");
}
__device__ __forceinline__ void ldsm4(uint32_t* d, uint32_t addr) {
    asm volatile("ldmatrix.sync.aligned.m8n8.x4.shared.b16 {%0,%1,%2,%3}, [%4];"
                 : "=r"(d[0]), "=r"(d[1]), "=r"(d[2]), "=r"(d[3]) : "r"(addr));
}
__device__ __forceinline__ void mma_f16(float* c, const uint32_t* a, const uint32_t* b) {
    asm volatile(
        "mma.sync.aligned.m16n8k16.row.col.f32.f16.f16.f32 "
        "{%0,%1,%2,%3}, {%4,%5,%6,%7}, {%8,%9}, {%0,%1,%2,%3};"
        : "+f"(c[0]), "+f"(c[1]), "+f"(c[2]), "+f"(c[3])
        : "r"(a[0]), "r"(a[1]), "r"(a[2]), "r"(a[3]), "r"(b[0]), "r"(b[1]));
}

// ---------------------------------------------------------------------------
// Kernel 1: NCHW fp32 -> NHWC fp16 transpose (validated)
// ---------------------------------------------------------------------------
__global__ void k_transpose(const float* __restrict__ x) {
    __shared__ float t[32][33];
    int n   = blockIdx.z;
    int hw0 = blockIdx.x * 32;
    int c0  = blockIdx.y * 32;
    int tx = threadIdx.x, ty = threadIdx.y;
    const float* xin = x + (size_t)n * CIN * HWSZ;
    #pragma unroll
    for (int i = 0; i < 4; i++) {
        int c = c0 + ty + i * 8;
        t[ty + i * 8][tx] = xin[(size_t)c * HWSZ + hw0 + tx];
    }
    __syncthreads();
    __half* xo = g_xh + (size_t)n * HWSZ * CIN;
    #pragma unroll
    for (int i = 0; i < 4; i++) {
        int hw = hw0 + ty + i * 8;
        xo[(size_t)hw * CIN + c0 + tx] = __float2half_rn(t[tx][ty + i * 8]);
    }
}

// ---------------------------------------------------------------------------
// Kernel 2: weight -> Bh[co][ker*256+ci] fp16
// ---------------------------------------------------------------------------
__global__ void k_wt(const float* __restrict__ w) {
    int idx = blockIdx.x * 256 + threadIdx.x;   // COUT*KD
    int kk = idx % KD;
    int co = idx / KD;
    int ker = kk >> 8;
    int ci  = kk & 255;
    g_Bh[idx] = __float2half_rn(w[((size_t)co * CIN + ci) * KKER + ker]);
}

// ---------------------------------------------------------------------------
// Kernel 3: bilinear gather (warp/pixel, 8ch/thread, uint4) — R10-validated
// ---------------------------------------------------------------------------
__global__ __launch_bounds__(256) void k_gather(const float* __restrict__ offset,
                                                const float* __restrict__ mask) {
    int tid  = threadIdx.x;
    int wpix = tid >> 5;
    int lane = tid & 31;
    int pix = blockIdx.x * 8 + wpix;
    int n   = pix / HWSZ;
    int hw  = pix % HWSZ;
    int ho  = hw / WW, wo = hw % WW;
    const __half* xb = g_xh + (size_t)n * HWSZ * CIN + lane * 8;
    __half* vout = g_Vh + (size_t)pix * KD + lane * 8;

    #pragma unroll
    for (int k = 0; k < KKER; k++) {
        float dy = __ldg(&offset[((size_t)n * 18 + 2 * k)     * HWSZ + hw]);
        float dx = __ldg(&offset[((size_t)n * 18 + 2 * k + 1) * HWSZ + hw]);
        float mm = __ldg(&mask  [((size_t)n * KKER + k)       * HWSZ + hw]);
        float py = dy + (float)(k / 3) + (float)(ho - 1);
        float px = dx + (float)(k % 3) + (float)(wo - 1);
        float fy = floorf(py), fx = floorf(px);
        int y0 = (int)fy, x0 = (int)fx;
        float wy1 = py - fy, wx1 = px - fx;
        float wy0 = 1.0f - wy1, wx0 = 1.0f - wx1;

        bool yv0 = (y0 >= 0) && (y0 < HH);
        bool yv1 = (y0 + 1 >= 0) && (y0 + 1 < HH);
        bool xv0 = (x0 >= 0) && (x0 < WW);
        bool xv1 = (x0 + 1 >= 0) && (x0 + 1 < WW);
        float w00 = (yv0 && xv0) ? wy0 * wx0 * mm : 0.0f;
        float w01 = (yv0 && xv1) ? wy0 * wx1 * mm : 0.0f;
        float w10 = (yv1 && xv0) ? wy1 * wx0 * mm : 0.0f;
        float w11 = (yv1 && xv1) ? wy1 * wx1 * mm : 0.0f;
        int yc0 = min(max(y0, 0), HH - 1), yc1 = min(max(y0 + 1, 0), HH - 1);
        int xc0 = min(max(x0, 0), WW - 1), xc1 = min(max(x0 + 1, 0), WW - 1);

        uint4 u00 = *reinterpret_cast<const uint4*>(xb + (size_t)(yc0 * WW + xc0) * CIN);
        uint4 u01 = *reinterpret_cast<const uint4*>(xb + (size_t)(yc0 * WW + xc1) * CIN);
        uint4 u10 = *reinterpret_cast<const uint4*>(xb + (size_t)(yc1 * WW + xc0) * CIN);
        uint4 u11 = *reinterpret_cast<const uint4*>(xb + (size_t)(yc1 * WW + xc1) * CIN);

        const __half2* h00 = reinterpret_cast<const __half2*>(&u00);
        const __half2* h01 = reinterpret_cast<const __half2*>(&u01);
        const __half2* h10 = reinterpret_cast<const __half2*>(&u10);
        const __half2* h11 = reinterpret_cast<const __half2*>(&u11);

        uint4 ro;
        __half2* hv = reinterpret_cast<__half2*>(&ro);
        #pragma unroll
        for (int s = 0; s < 4; s++) {
            float2 c00 = __half22float2(h00[s]);
            float2 c01 = __half22float2(h01[s]);
            float2 c10 = __half22float2(h10[s]);
            float2 c11 = __half22float2(h11[s]);
            float2 r;
            r.x = w00 * c00.x + w01 * c01.x + w10 * c10.x + w11 * c11.x;
            r.y = w00 * c00.y + w01 * c01.y + w10 * c10.y + w11 * c11.y;
            hv[s] = __float22half2_rn(r);
        }
        *reinterpret_cast<uint4*>(vout + k * CIN) = ro;
    }
}

// ---------------------------------------------------------------------------
// Kernel 4: fp16 HMMA GEMM  C[25088,256] = Vh * Bh^T  (+bias)
// BM=64, BN=128, BK=32, 256 thr, 8 warps (2M x 4N), warp tile 32x32,
// 4-stage cp.async, 3 CTAs/SM, REGISTER-FRAGMENT DOUBLE BUFFERING.
// ---------------------------------------------------------------------------
#define BK 32
#define NCHUNK (KD / BK)        // 72
#define ROWB 80
#define A_MAT (64 * ROWB)       // 5120
#define B_MAT (128 * ROWB)      // 10240
#define OFF_A 0
#define OFF_B A_MAT
#define STAGE_BYTES (A_MAT + B_MAT)             // 15360
#define NSTAGE 4
#define SMEM_TOTAL (NSTAGE * STAGE_BYTES)       // 61440

__global__ __launch_bounds__(256, 3) void k_gemm(const float* __restrict__ bias,
                                                 float* __restrict__ out) {
    extern __shared__ char smem[];
    uint32_t sbase = smem_u32(smem);
    int tid  = threadIdx.x;
    int lane = tid & 31;
    int wid  = tid >> 5;
    int wm   = wid & 1;
    int wn   = wid >> 1;
    int n0 = blockIdx.x * 128;
    int m0 = blockIdx.y * 64;

    const __half* Ag = g_Vh + (size_t)m0 * KD;
    const __half* Bg = g_Bh + (size_t)n0 * KD;

    int a_row = tid >> 2;
    int a_seg = tid & 3;
    int b_row0 = tid >> 2;
    int b_seg  = tid & 3;

    auto issue = [&](int kt) {
        uint32_t sb = sbase + (kt % NSTAGE) * STAGE_BYTES;
        int kel = kt * BK;
        cp_async16(sb + OFF_A + a_row * ROWB + a_seg * 16,
                   Ag + (size_t)a_row * KD + kel + a_seg * 8);
        #pragma unroll
        for (int r = 0; r < 2; r++) {
            int row = b_row0 + r * 64;
            cp_async16(sb + OFF_B + row * ROWB + b_seg * 16,
                       Bg + (size_t)row * KD + kel + b_seg * 8);
        }
    };

    float acc[2][4][4];
    #pragma unroll
    for (int i = 0; i < 2; i++)
        #pragma unroll
        for (int j = 0; j < 4; j++)
            #pragma unroll
            for (int r = 0; r < 4; r++) acc[i][j][r] = 0.0f;

    int a_lrow = (lane & 7) + ((lane >> 3) & 1) * 8;
    int a_lc   = (lane >> 4) & 1;
    int b_lrow = (lane & 7) + ((lane >> 4) & 1) * 8;
    int b_lc   = (lane >> 3) & 1;

    // fragment addresses (fixed per ks within a stage)
    int arow0 = wm * 32 + a_lrow;          // +16 for mt=1
    int brow0 = wn * 32 + b_lrow;          // +16 for pg=1

    auto load_frags = [&](uint32_t sb, int ks, uint32_t A0[4], uint32_t A1[4],
                          uint32_t B0[4], uint32_t B1[4]) {
        int c = 2 * ks;
        ldsm4(A0, sb + OFF_A + arow0 * ROWB + (c + a_lc) * 16);
        ldsm4(A1, sb + OFF_A + (arow0 + 16) * ROWB + (c + a_lc) * 16);
        ldsm4(B0, sb + OFF_B + brow0 * ROWB + (c + b_lc) * 16);
        ldsm4(B1, sb + OFF_B + (brow0 + 16) * ROWB + (c + b_lc) * 16);
    };
    auto compute = [&](uint32_t A0[4], uint32_t A1[4], uint32_t B0[4], uint32_t B1[4]) {
        uint32_t* Bp[2] = {B0, B1};
        #pragma unroll
        for (int nt = 0; nt < 4; nt++) {
            const uint32_t* b = &Bp[nt >> 1][(nt & 1) * 2];
            mma_f16(acc[0][nt], A0, b);
            mma_f16(acc[1][nt], A1, b);
        }
    };

    issue(0); cp_commit();
    issue(1); cp_commit();
    issue(2); cp_commit();

    uint32_t Fa0[4], Fa1[4], Fb0[4], Fb1[4];   // buffer 0
    uint32_t Ga0[4], Ga1[4], Gb0[4], Gb1[4];   // buffer 1

    for (int kt = 0; kt < NCHUNK; kt++) {
        cp_wait<2>();
        __syncthreads();
        if (kt + 3 < NCHUNK) issue(kt + 3);
        cp_commit();

        uint32_t sb = sbase + (kt % NSTAGE) * STAGE_BYTES;
        // preload ks=0 frags, then prefetch ks=1 while computing ks=0
        load_frags(sb, 0, Fa0, Fa1, Fb0, Fb1);
        load_frags(sb, 1, Ga0, Ga1, Gb0, Gb1);
        compute(Fa0, Fa1, Fb0, Fb1);
        compute(Ga0, Ga1, Gb0, Gb1);
    }

    // epilogue: transpose through smem -> coalesced NCHW float4 writes
    __syncthreads();
    float* ep = reinterpret_cast<float*>(smem);   // [128 co][68 m]
    #pragma unroll
    for (int mt = 0; mt < 2; mt++)
        #pragma unroll
        for (int nt = 0; nt < 4; nt++)
            #pragma unroll
            for (int r = 0; r < 4; r++) {
                int m_l  = wm * 32 + mt * 16 + (lane >> 2) + ((r >> 1) ? 8 : 0);
                int co_l = wn * 32 + nt * 8 + (lane & 3) * 2 + (r & 1);
                ep[co_l * 68 + m_l] = acc[mt][nt][r];
            }
    __syncthreads();
    int img  = m0 / HWSZ;
    int hw0c = m0 - img * HWSZ;
    #pragma unroll
    for (int it = 0; it < 8; it++) {
        int idx = tid + it * 256;
        int co  = idx >> 4;
        int mq  = (idx & 15) * 4;
        float4 v = *reinterpret_cast<float4*>(&ep[co * 68 + mq]);
        float bv = bias[n0 + co];
        v.x += bv; v.y += bv; v.z += bv; v.w += bv;
        float* op = out + ((size_t)img * COUT + n0 + co) * HWSZ + hw0c + mq;
        *reinterpret_cast<float4*>(op) = v;
    }
}

// ---------------------------------------------------------------------------
// Launch
// ---------------------------------------------------------------------------
extern "C" void kernel_launch(void* const* d_in, const int* in_sizes, int n_in,
                              void* d_out, int out_size) {
    const float* x      = (const float*)d_in[0];
    const float* offset = (const float*)d_in[1];
    const float* mask   = (const float*)d_in[2];
    const float* weight = (const float*)d_in[3];
    const float* bias   = (const float*)d_in[4];
    float* out = (float*)d_out;

    {
        dim3 grid(HWSZ / 32, CIN / 32, NN);
        dim3 block(32, 8);
        k_transpose<<<grid, block>>>(x);
    }
    k_wt<<<KD, 256>>>(weight);
    k_gather<<<M_TOTAL / 8, 256>>>(offset, mask);
    {
        static bool attr_set = false;
        if (!attr_set) {
            cudaFuncSetAttribute(k_gemm,
                                 cudaFuncAttributeMaxDynamicSharedMemorySize,
                                 SMEM_TOTAL);
            attr_set = true;
        }
        dim3 grid(COUT / 128, M_TOTAL / 64);   // 2 x 392
        k_gemm<<<grid, 256, SMEM_TOTAL>>>(bias, out);
    }
}

// round 13
// speedup vs baseline: 1.0120x; 1.0120x over previous
#include <cuda_runtime.h>
#include <cuda_fp16.h>
#include <cstdint>

#define CIN 256
#define COUT 256
#define HH 56
#define WW 56
#define NN 8
#define KKER 9
#define HWSZ (HH*WW)            // 3136
#define M_TOTAL (NN*HWSZ)       // 25088
#define KD (KKER*CIN)           // 2304

// Scratch (device globals — no runtime allocation allowed)
__device__ __half g_xh[(size_t)NN*HWSZ*CIN];        // 12.8 MB fp16 NHWC
__device__ __half g_Vh[(size_t)M_TOTAL*KD];         // 115.6 MB fp16
__device__ __half g_Bh[(size_t)COUT*KD];            // 1.18 MB fp16

// ---------------------------------------------------------------------------
// helpers
// ---------------------------------------------------------------------------
__device__ __forceinline__ uint32_t smem_u32(const void* p) {
    uint32_t a;
    asm("{ .reg .u64 t; cvta.to.shared.u64 t, %1; cvt.u32.u64 %0, t; }"
        : "=r"(a) : "l"(p));
    return a;
}
__device__ __forceinline__ void cp_async16(uint32_t saddr, const void* gptr) {
    asm volatile("cp.async.cg.shared.global [%0], [%1], 16;"
                 :: "r"(saddr), "l"(__cvta_generic_to_global(gptr)) : "memory");
}
__device__ __forceinline__ void cp_commit() {
    asm volatile("cp.async.commit_group;" ::: "memory");
}
template <int N>
__device__ __forceinline__ void cp_wait() {
    asm volatile("cp.async.wait_group %0;" :: "n"(N) : "memory");
}
__device__ __forceinline__ void ldsm4(uint32_t* d, uint32_t addr) {
    asm volatile("ldmatrix.sync.aligned.m8n8.x4.shared.b16 {%0,%1,%2,%3}, [%4];"
                 : "=r"(d[0]), "=r"(d[1]), "=r"(d[2]), "=r"(d[3]) : "r"(addr));
}
__device__ __forceinline__ void mma_f16(float* c, const uint32_t* a, const uint32_t* b) {
    asm volatile(
        "mma.sync.aligned.m16n8k16.row.col.f32.f16.f16.f32 "
        "{%0,%1,%2,%3}, {%4,%5,%6,%7}, {%8,%9}, {%0,%1,%2,%3};"
        : "+f"(c[0]), "+f"(c[1]), "+f"(c[2]), "+f"(c[3])
        : "r"(a[0]), "r"(a[1]), "r"(a[2]), "r"(a[3]), "r"(b[0]), "r"(b[1]));
}

// ---------------------------------------------------------------------------
// Kernel 1: NCHW fp32 -> NHWC fp16 transpose (validated)
// ---------------------------------------------------------------------------
__global__ void k_transpose(const float* __restrict__ x) {
    __shared__ float t[32][33];
    int n   = blockIdx.z;
    int hw0 = blockIdx.x * 32;
    int c0  = blockIdx.y * 32;
    int tx = threadIdx.x, ty = threadIdx.y;
    const float* xin = x + (size_t)n * CIN * HWSZ;
    #pragma unroll
    for (int i = 0; i < 4; i++) {
        int c = c0 + ty + i * 8;
        t[ty + i * 8][tx] = xin[(size_t)c * HWSZ + hw0 + tx];
    }
    __syncthreads();
    __half* xo = g_xh + (size_t)n * HWSZ * CIN;
    #pragma unroll
    for (int i = 0; i < 4; i++) {
        int hw = hw0 + ty + i * 8;
        xo[(size_t)hw * CIN + c0 + tx] = __float2half_rn(t[tx][ty + i * 8]);
    }
}

// ---------------------------------------------------------------------------
// Kernel 2: weight -> Bh[co][ker*256+ci] fp16
// ---------------------------------------------------------------------------
__global__ void k_wt(const float* __restrict__ w) {
    int idx = blockIdx.x * 256 + threadIdx.x;   // COUT*KD
    int kk = idx % KD;
    int co = idx / KD;
    int ker = kk >> 8;
    int ci  = kk & 255;
    g_Bh[idx] = __float2half_rn(w[((size_t)co * CIN + ci) * KKER + ker]);
}

// ---------------------------------------------------------------------------
// Kernel 3: bilinear gather (warp/pixel, 8ch/thread, uint4) — R10-validated
// ---------------------------------------------------------------------------
__global__ __launch_bounds__(256) void k_gather(const float* __restrict__ offset,
                                                const float* __restrict__ mask) {
    int tid  = threadIdx.x;
    int wpix = tid >> 5;
    int lane = tid & 31;
    int pix = blockIdx.x * 8 + wpix;
    int n   = pix / HWSZ;
    int hw  = pix % HWSZ;
    int ho  = hw / WW, wo = hw % WW;
    const __half* xb = g_xh + (size_t)n * HWSZ * CIN + lane * 8;
    __half* vout = g_Vh + (size_t)pix * KD + lane * 8;

    #pragma unroll
    for (int k = 0; k < KKER; k++) {
        float dy = __ldg(&offset[((size_t)n * 18 + 2 * k)     * HWSZ + hw]);
        float dx = __ldg(&offset[((size_t)n * 18 + 2 * k + 1) * HWSZ + hw]);
        float mm = __ldg(&mask  [((size_t)n * KKER + k)       * HWSZ + hw]);
        float py = dy + (float)(k / 3) + (float)(ho - 1);
        float px = dx + (float)(k % 3) + (float)(wo - 1);
        float fy = floorf(py), fx = floorf(px);
        int y0 = (int)fy, x0 = (int)fx;
        float wy1 = py - fy, wx1 = px - fx;
        float wy0 = 1.0f - wy1, wx0 = 1.0f - wx1;

        bool yv0 = (y0 >= 0) && (y0 < HH);
        bool yv1 = (y0 + 1 >= 0) && (y0 + 1 < HH);
        bool xv0 = (x0 >= 0) && (x0 < WW);
        bool xv1 = (x0 + 1 >= 0) && (x0 + 1 < WW);
        float w00 = (yv0 && xv0) ? wy0 * wx0 * mm : 0.0f;
        float w01 = (yv0 && xv1) ? wy0 * wx1 * mm : 0.0f;
        float w10 = (yv1 && xv0) ? wy1 * wx0 * mm : 0.0f;
        float w11 = (yv1 && xv1) ? wy1 * wx1 * mm : 0.0f;
        int yc0 = min(max(y0, 0), HH - 1), yc1 = min(max(y0 + 1, 0), HH - 1);
        int xc0 = min(max(x0, 0), WW - 1), xc1 = min(max(x0 + 1, 0), WW - 1);

        uint4 u00 = *reinterpret_cast<const uint4*>(xb + (size_t)(yc0 * WW + xc0) * CIN);
        uint4 u01 = *reinterpret_cast<const uint4*>(xb + (size_t)(yc0 * WW + xc1) * CIN);
        uint4 u10 = *reinterpret_cast<const uint4*>(xb + (size_t)(yc1 * WW + xc0) * CIN);
        uint4 u11 = *reinterpret_cast<const uint4*>(xb + (size_t)(yc1 * WW + xc1) * CIN);

        const __half2* h00 = reinterpret_cast<const __half2*>(&u00);
        const __half2* h01 = reinterpret_cast<const __half2*>(&u01);
        const __half2* h10 = reinterpret_cast<const __half2*>(&u10);
        const __half2* h11 = reinterpret_cast<const __half2*>(&u11);

        uint4 ro;
        __half2* hv = reinterpret_cast<__half2*>(&ro);
        #pragma unroll
        for (int s = 0; s < 4; s++) {
            float2 c00 = __half22float2(h00[s]);
            float2 c01 = __half22float2(h01[s]);
            float2 c10 = __half22float2(h10[s]);
            float2 c11 = __half22float2(h11[s]);
            float2 r;
            r.x = w00 * c00.x + w01 * c01.x + w10 * c10.x + w11 * c11.x;
            r.y = w00 * c00.y + w01 * c01.y + w10 * c10.y + w11 * c11.y;
            hv[s] = __float22half2_rn(r);
        }
        *reinterpret_cast<uint4*>(vout + k * CIN) = ro;
    }
}

// ---------------------------------------------------------------------------
// Kernel 4: fp16 HMMA GEMM  C[25088,256] = Vh * Bh^T  (+bias)
// BM=64, BN=128, BK=64, 256 thr, 8 warps (2M x 4N), warp tile 32x32,
// 2-stage cp.async (depth-1 prefetch), 3 CTAs/SM.
// FIX vs R12: cp_commit() unconditional so group counting stays aligned.
// ---------------------------------------------------------------------------
#define BK 64
#define NCHUNK (KD / BK)        // 36
#define ROWB 144                // 64 fp16 = 128B data + 16B pad
#define A_MAT (64 * ROWB)       // 9216
#define B_MAT (128 * ROWB)      // 18432
#define OFF_A 0
#define OFF_B A_MAT
#define STAGE_BYTES (A_MAT + B_MAT)             // 27648
#define NSTAGE 2
#define SMEM_TOTAL (NSTAGE * STAGE_BYTES)       // 55296

__global__ __launch_bounds__(256, 3) void k_gemm(const float* __restrict__ bias,
                                                 float* __restrict__ out) {
    extern __shared__ char smem[];
    uint32_t sbase = smem_u32(smem);
    int tid  = threadIdx.x;
    int lane = tid & 31;
    int wid  = tid >> 5;
    int wm   = wid & 1;
    int wn   = wid >> 1;
    int n0 = blockIdx.x * 128;
    int m0 = blockIdx.y * 64;

    const __half* Ag = g_Vh + (size_t)m0 * KD;
    const __half* Bg = g_Bh + (size_t)n0 * KD;

    int a_row0 = tid >> 3;       // 0..31, +32
    int a_seg  = tid & 7;
    int b_row0 = tid >> 3;       // 0..31, +32,+64,+96
    int b_seg  = tid & 7;

    auto issue = [&](int kt) {
        uint32_t sb = sbase + (kt & 1) * STAGE_BYTES;
        int kel = kt * BK;
        #pragma unroll
        for (int r = 0; r < 2; r++) {
            int row = a_row0 + r * 32;
            cp_async16(sb + OFF_A + row * ROWB + a_seg * 16,
                       Ag + (size_t)row * KD + kel + a_seg * 8);
        }
        #pragma unroll
        for (int r = 0; r < 4; r++) {
            int row = b_row0 + r * 32;
            cp_async16(sb + OFF_B + row * ROWB + b_seg * 16,
                       Bg + (size_t)row * KD + kel + b_seg * 8);
        }
    };

    float acc[2][4][4];
    #pragma unroll
    for (int i = 0; i < 2; i++)
        #pragma unroll
        for (int j = 0; j < 4; j++)
            #pragma unroll
            for (int r = 0; r < 4; r++) acc[i][j][r] = 0.0f;

    int a_lrow = (lane & 7) + ((lane >> 3) & 1) * 8;
    int a_lc   = (lane >> 4) & 1;
    int b_lrow = (lane & 7) + ((lane >> 4) & 1) * 8;
    int b_lc   = (lane >> 3) & 1;
    int arow0 = wm * 32 + a_lrow;
    int brow0 = wn * 32 + b_lrow;

    issue(0); cp_commit();

    for (int kt = 0; kt < NCHUNK; kt++) {
        if (kt + 1 < NCHUNK) issue(kt + 1);
        cp_commit();                       // unconditional: keeps group count aligned
        cp_wait<1>();
        __syncthreads();

        uint32_t sb = sbase + (kt & 1) * STAGE_BYTES;
        #pragma unroll
        for (int ks = 0; ks < 4; ks++) {
            uint32_t Ah[2][4], Bt[2][4];
            int c = 2 * ks;
            ldsm4(Ah[0], sb + OFF_A + arow0 * ROWB + (c + a_lc) * 16);
            ldsm4(Ah[1], sb + OFF_A + (arow0 + 16) * ROWB + (c + a_lc) * 16);
            ldsm4(Bt[0], sb + OFF_B + brow0 * ROWB + (c + b_lc) * 16);
            ldsm4(Bt[1], sb + OFF_B + (brow0 + 16) * ROWB + (c + b_lc) * 16);
            #pragma unroll
            for (int nt = 0; nt < 4; nt++) {
                const uint32_t* b = &Bt[nt >> 1][(nt & 1) * 2];
                mma_f16(acc[0][nt], Ah[0], b);
                mma_f16(acc[1][nt], Ah[1], b);
            }
        }
        __syncthreads();
    }

    // epilogue: transpose through smem -> coalesced NCHW float4 writes
    float* ep = reinterpret_cast<float*>(smem);   // [128 co][68 m] = 34.8KB
    #pragma unroll
    for (int mt = 0; mt < 2; mt++)
        #pragma unroll
        for (int nt = 0; nt < 4; nt++)
            #pragma unroll
            for (int r = 0; r < 4; r++) {
                int m_l  = wm * 32 + mt * 16 + (lane >> 2) + ((r >> 1) ? 8 : 0);
                int co_l = wn * 32 + nt * 8 + (lane & 3) * 2 + (r & 1);
                ep[co_l * 68 + m_l] = acc[mt][nt][r];
            }
    __syncthreads();
    int img  = m0 / HWSZ;
    int hw0c = m0 - img * HWSZ;
    #pragma unroll
    for (int it = 0; it < 8; it++) {
        int idx = tid + it * 256;
        int co  = idx >> 4;
        int mq  = (idx & 15) * 4;
        float4 v = *reinterpret_cast<float4*>(&ep[co * 68 + mq]);
        float bv = bias[n0 + co];
        v.x += bv; v.y += bv; v.z += bv; v.w += bv;
        float* op = out + ((size_t)img * COUT + n0 + co) * HWSZ + hw0c + mq;
        *reinterpret_cast<float4*>(op) = v;
    }
}

// ---------------------------------------------------------------------------
// Launch
// ---------------------------------------------------------------------------
extern "C" void kernel_launch(void* const* d_in, const int* in_sizes, int n_in,
                              void* d_out, int out_size) {
    const float* x      = (const float*)d_in[0];
    const float* offset = (const float*)d_in[1];
    const float* mask   = (const float*)d_in[2];
    const float* weight = (const float*)d_in[3];
    const float* bias   = (const float*)d_in[4];
    float* out = (float*)d_out;

    {
        dim3 grid(HWSZ / 32, CIN / 32, NN);
        dim3 block(32, 8);
        k_transpose<<<grid, block>>>(x);
    }
    k_wt<<<KD, 256>>>(weight);
    k_gather<<<M_TOTAL / 8, 256>>>(offset, mask);
    {
        static bool attr_set = false;
        if (!attr_set) {
            cudaFuncSetAttribute(k_gemm,
                                 cudaFuncAttributeMaxDynamicSharedMemorySize,
                                 SMEM_TOTAL);
            attr_set = true;
        }
        dim3 grid(COUT / 128, M_TOTAL / 64);   // 2 x 392
        k_gemm<<<grid, 256, SMEM_TOTAL>>>(bias, out);
    }
}